// round 5
// baseline (speedup 1.0000x reference)
#include <cuda_runtime.h>
#include <cstdint>

#define B_   64
#define T_   4096
#define H_   128
#define C1_  64
#define NCLS_ 40
#define NROWS (B_ * T_)          // 262144
#define NSTAT_BLK 128

// ---------------- device scratch (no allocations allowed) ----------------
__device__ float g_part[NSTAT_BLK * 9];  // per-block partial moments of x
__device__ float g_cw[C1_ * 3];          // conv weights folded with BN scale
__device__ float g_cb[C1_];              // conv bias folded with BN scale+shift

// ---------------- helpers ----------------
__device__ __forceinline__ float sig_fast(float v) {
    return __fdividef(1.f, 1.f + __expf(-v));
}
__device__ __forceinline__ float tanh_fast(float v) {
    return __fdividef(2.f, 1.f + __expf(-2.f * v)) - 1.f;
}
__device__ __forceinline__ uint32_t smem_u32(const void* p) {
    return (uint32_t)__cvta_generic_to_shared(p);
}
__device__ __forceinline__ uint32_t mapa_u32(uint32_t addr, uint32_t rank) {
    uint32_t r;
    asm("mapa.shared::cluster.u32 %0, %1, %2;" : "=r"(r) : "r"(addr), "r"(rank));
    return r;
}
__device__ __forceinline__ void st_remote_f32(uint32_t addr, float v) {
    asm volatile("st.shared::cluster.f32 [%0], %1;" :: "r"(addr), "f"(v) : "memory");
}
__device__ __forceinline__ void mbar_init(uint32_t addr, uint32_t cnt) {
    asm volatile("mbarrier.init.shared.b64 [%0], %1;" :: "r"(addr), "r"(cnt) : "memory");
}
__device__ __forceinline__ void mbar_arrive_remote(uint32_t addr) {
    asm volatile("mbarrier.arrive.shared::cluster.b64 _, [%0];" :: "r"(addr) : "memory");
}
__device__ __forceinline__ void mbar_wait(uint32_t addr, uint32_t parity) {
    asm volatile(
        "{\n\t"
        ".reg .pred P;\n\t"
        "WAITLOOP_%=:\n\t"
        "mbarrier.try_wait.parity.acquire.cta.shared::cta.b64 P, [%0], %1, 0x989680;\n\t"
        "@P bra.uni WAITDONE_%=;\n\t"
        "bra.uni WAITLOOP_%=;\n\t"
        "WAITDONE_%=:\n\t"
        "}\n\t"
        :: "r"(addr), "r"(parity) : "memory");
}
__device__ __forceinline__ void fence_cluster() {
    asm volatile("fence.acq_rel.cluster;" ::: "memory");
}
__device__ __forceinline__ void cluster_barrier() {
    asm volatile("barrier.cluster.arrive.aligned;" ::: "memory");
    asm volatile("barrier.cluster.wait.aligned;" ::: "memory");
}

// ---------------- kernel 1: second moments of x over (B,T) ----------------
__global__ void __launch_bounds__(256) stats_kernel(const float* __restrict__ x) {
    __shared__ float red[256];
    float s0=0,s1=0,s2=0,s3=0,s4=0,s5=0,s6=0,s7=0,s8=0;
    const int stride = NSTAT_BLK * 256;
    for (int i = blockIdx.x * 256 + threadIdx.x; i < NROWS; i += stride) {
        float a = x[i*3+0], b = x[i*3+1], c = x[i*3+2];
        s0 += a;   s1 += b;   s2 += c;
        s3 += a*a; s4 += a*b; s5 += a*c;
        s6 += b*b; s7 += b*c; s8 += c*c;
    }
    float sv[9] = {s0,s1,s2,s3,s4,s5,s6,s7,s8};
    #pragma unroll 1
    for (int j = 0; j < 9; j++) {
        red[threadIdx.x] = sv[j];
        __syncthreads();
        for (int o = 128; o > 0; o >>= 1) {
            if (threadIdx.x < o) red[threadIdx.x] += red[threadIdx.x + o];
            __syncthreads();
        }
        if (threadIdx.x == 0) g_part[blockIdx.x * 9 + j] = red[0];
        __syncthreads();
    }
}

// ---------------- kernel 2: fold BN (derived analytically) into conv ----------------
__global__ void __launch_bounds__(64) fold_kernel(const float* __restrict__ conv_w,
                                                  const float* __restrict__ conv_b,
                                                  const float* __restrict__ gamma,
                                                  const float* __restrict__ beta) {
    __shared__ float st[9];
    if (threadIdx.x < 9) {
        float s = 0.f;
        for (int i = 0; i < NSTAT_BLK; i++) s += g_part[i * 9 + threadIdx.x];
        st[threadIdx.x] = s;
    }
    __syncthreads();
    const int c = threadIdx.x;
    const float N = (float)NROWS;
    float m0 = st[0]/N, m1 = st[1]/N, m2 = st[2]/N;
    float C00 = st[3]/N - m0*m0, C01 = st[4]/N - m0*m1, C02 = st[5]/N - m0*m2;
    float C11 = st[6]/N - m1*m1, C12 = st[7]/N - m1*m2, C22 = st[8]/N - m2*m2;
    float w0 = conv_w[c*3+0], w1 = conv_w[c*3+1], w2 = conv_w[c*3+2];
    // y = x.w + b  ->  mean_y = w.m + b ; var_y = w^T Cov w (exact, linear map)
    float mean = w0*m0 + w1*m1 + w2*m2 + conv_b[c];
    float var  = w0*w0*C00 + w1*w1*C11 + w2*w2*C22
               + 2.f*(w0*w1*C01 + w0*w2*C02 + w1*w2*C12);
    float sc = gamma[c] * rsqrtf(var + 1e-5f);
    g_cw[c*3+0] = w0 * sc;
    g_cw[c*3+1] = w1 * sc;
    g_cw[c*3+2] = w2 * sc;
    g_cb[c]     = conv_b[c] * sc + (beta[c] - mean * sc);
}

// ---------------- kernel 3: persistent clustered LSTM ----------------
// Grid: 128 CTAs, cluster=(2,1,1). Cluster k owns batch row k/... :
//   blockIdx.x>>1 = batch row b ; blockIdx.x&1 = half (which 64 hidden units).
// 256 threads/CTA, thread owns ONE gate row r: W_hh[r][0:128] + W_ih[r][0:64] in registers.
__global__ void __cluster_dims__(2, 1, 1) __launch_bounds__(256, 1)
lstm_kernel(const float* __restrict__ x,
            const float* __restrict__ w_ih, const float* __restrict__ b_ih,
            const float* __restrict__ w_hh, const float* __restrict__ b_hh,
            const float* __restrict__ out_w, const float* __restrict__ out_b,
            const float* __restrict__ h0, const float* __restrict__ c0,
            float* __restrict__ out) {
    __shared__ __align__(16) float h_s[2][H_];   // double-buffered full h
    __shared__ float c_s[64];                    // own half of c
    __shared__ __align__(16) float y_s[C1_];     // conv/BN/relu output, current step
    __shared__ float act_s[256];                 // activated gates
    __shared__ __align__(8) unsigned long long mbar[1];

    const int tid  = threadIdx.x;
    const int b    = blockIdx.x >> 1;
    const int half = blockIdx.x & 1;
    const int q    = tid >> 6;        // gate: 0=i 1=f 2=g 3=o
    const int jj   = tid & 63;        // hidden index within half
    const int r    = q * H_ + half * 64 + jj;   // global gate row in [0,512)

    // load weights into registers (one-time)
    float whh[H_];
    #pragma unroll
    for (int k = 0; k < H_; k++) whh[k] = __ldg(&w_hh[r * H_ + k]);
    float wih[C1_];
    #pragma unroll
    for (int c = 0; c < C1_; c++) wih[c] = __ldg(&w_ih[r * C1_ + c]);
    const float bias = b_ih[r] + b_hh[r];

    if (tid < H_) h_s[0][tid] = h0[b * H_ + tid];
    if (tid < 64) c_s[tid] = c0[b * H_ + half * 64 + tid];

    const float* xb = x + (size_t)b * T_ * 3;
    if (tid >= 64 && tid < 128) {   // y(0)
        int ch = tid - 64;
        float v = fmaf(g_cw[ch*3+2], xb[2],
                  fmaf(g_cw[ch*3+1], xb[1],
                  fmaf(g_cw[ch*3+0], xb[0], g_cb[ch])));
        y_s[ch] = fmaxf(v, 0.f);
    }

    const uint32_t mbar_a    = smem_u32(mbar);
    const uint32_t peer_mbar = mapa_u32(mbar_a, (uint32_t)(half ^ 1));
    const uint32_t peer_h    = mapa_u32(smem_u32(&h_s[0][0]), (uint32_t)(half ^ 1));

    if (tid == 0) mbar_init(mbar_a, 1);
    __syncthreads();
    cluster_barrier();   // mbar init visible cluster-wide before any arrive

    uint32_t parity = 0;
    const float* xp = xb + 3;

    #pragma unroll 1
    for (int t = 0; t < T_; t++) {
        // ---- input-side partial gates (does not need h -> hides sync) ----
        float acc0 = bias, acc1 = 0.f;
        const float4* y4 = (const float4*)y_s;
        #pragma unroll
        for (int c = 0; c < C1_; c += 4) {
            float4 yv = y4[c >> 2];
            acc0 = fmaf(wih[c+0], yv.x, acc0);
            acc1 = fmaf(wih[c+1], yv.y, acc1);
            acc0 = fmaf(wih[c+2], yv.z, acc0);
            acc1 = fmaf(wih[c+3], yv.w, acc1);
        }
        // prefetch x(t+1)
        float px0 = 0.f, px1 = 0.f, px2 = 0.f;
        const bool doy = (tid >= 64 && tid < 128 && t < T_ - 1);
        if (doy) { px0 = xp[0]; px1 = xp[1]; px2 = xp[2]; }

        // ---- wait for peer half of h(t) ----
        if (t > 0) {
            mbar_wait(mbar_a, parity);
            parity ^= 1;
            fence_cluster();
        }
        const int cur = t & 1;
        const float4* h4 = (const float4*)h_s[cur];
        #pragma unroll
        for (int k = 0; k < H_; k += 4) {
            float4 hv = h4[k >> 2];
            acc0 = fmaf(whh[k+0], hv.x, acc0);
            acc1 = fmaf(whh[k+1], hv.y, acc1);
            acc0 = fmaf(whh[k+2], hv.z, acc0);
            acc1 = fmaf(whh[k+3], hv.w, acc1);
        }
        float a = acc0 + acc1;
        a = (q == 2) ? tanh_fast(a) : sig_fast(a);
        act_s[tid] = a;
        __syncthreads();

        const int nxt = cur ^ 1;
        if (tid < 64) {
            // c/h update for own half
            float cc = fmaf(act_s[64 + jj], c_s[jj], act_s[jj] * act_s[128 + jj]);
            c_s[jj] = cc;
            float hn = act_s[192 + jj] * tanh_fast(cc);
            int hj = half * 64 + jj;
            h_s[nxt][hj] = hn;
            st_remote_f32(peer_h + (uint32_t)(nxt * H_ + hj) * 4u, hn);
        } else if (doy) {
            // conv+BN+relu for step t+1 (overlaps with the h/c update warps)
            int ch = tid - 64;
            float v = fmaf(g_cw[ch*3+2], px2,
                      fmaf(g_cw[ch*3+1], px1,
                      fmaf(g_cw[ch*3+0], px0, g_cb[ch])));
            y_s[ch] = fmaxf(v, 0.f);
        }
        __syncthreads();
        if (tid == 0) {
            fence_cluster();           // make DSMEM h stores cluster-visible
            mbar_arrive_remote(peer_mbar);
        }
        xp += 3;
    }

    // final exchange: h(T) complete in h_s[0] (T even)
    mbar_wait(mbar_a, parity);
    fence_cluster();

    if (half == 0 && tid < NCLS_) {
        float acc = out_b[tid];
        #pragma unroll 4
        for (int k = 0; k < H_; k++)
            acc = fmaf(h_s[0][k], out_w[tid * H_ + k], acc);
        out[b * NCLS_ + tid] = acc;
    }
    cluster_barrier();   // clean cluster teardown
}

// ---------------- launch ----------------
extern "C" void kernel_launch(void* const* d_in, const int* in_sizes, int n_in,
                              void* d_out, int out_size) {
    const float* x      = (const float*)d_in[0];
    const float* conv_w = (const float*)d_in[1];
    const float* conv_b = (const float*)d_in[2];
    const float* bn_g   = (const float*)d_in[3];
    const float* bn_b   = (const float*)d_in[4];
    const float* w_ih   = (const float*)d_in[5];
    const float* b_ih   = (const float*)d_in[6];
    const float* w_hh   = (const float*)d_in[7];
    const float* b_hh   = (const float*)d_in[8];
    const float* out_w  = (const float*)d_in[9];
    const float* out_b  = (const float*)d_in[10];
    const float* h0     = (const float*)d_in[11];
    const float* c0     = (const float*)d_in[12];
    float* out = (float*)d_out;

    stats_kernel<<<NSTAT_BLK, 256>>>(x);
    fold_kernel<<<1, 64>>>(conv_w, conv_b, bn_g, bn_b);
    lstm_kernel<<<2 * B_, 256>>>(x, w_ih, b_ih, w_hh, b_hh,
                                 out_w, out_b, h0, c0, out);
}

// round 7
// speedup vs baseline: 1.8737x; 1.8737x over previous
#include <cuda_runtime.h>
#include <cstdint>

#define B_   64
#define T_   4096
#define H_   128
#define C1_  64
#define NCLS_ 40
#define NROWS (B_ * T_)          // 262144
#define NSTAT_BLK 128

// ---------------- device scratch (no allocations allowed) ----------------
__device__ float g_part[NSTAT_BLK * 9];  // per-block partial moments of x
__device__ float g_cw[C1_ * 3];          // conv weights folded with BN scale
__device__ float g_cb[C1_];              // conv bias folded with BN scale+shift

// ---------------- helpers ----------------
__device__ __forceinline__ float sig_fast(float v) {
    return __fdividef(1.f, 1.f + __expf(-v));
}
__device__ __forceinline__ float tanh_fast(float v) {
    return __fdividef(2.f, 1.f + __expf(-2.f * v)) - 1.f;
}
__device__ __forceinline__ uint32_t smem_u32(const void* p) {
    return (uint32_t)__cvta_generic_to_shared(p);
}
__device__ __forceinline__ uint32_t mapa_u32(uint32_t addr, uint32_t rank) {
    uint32_t r;
    asm("mapa.shared::cluster.u32 %0, %1, %2;" : "=r"(r) : "r"(addr), "r"(rank));
    return r;
}
// async store to peer SMEM with tx-completion on the peer's mbarrier:
// one remote landing, no fences, TMA-style visibility via the barrier.
__device__ __forceinline__ void st_async_remote_f32(uint32_t addr, float v, uint32_t mbar) {
    asm volatile("st.async.shared::cluster.mbarrier::complete_tx::bytes.f32 [%0], %1, [%2];"
                 :: "r"(addr), "f"(v), "r"(mbar) : "memory");
}
__device__ __forceinline__ void mbar_init(uint32_t addr, uint32_t cnt) {
    asm volatile("mbarrier.init.shared.b64 [%0], %1;" :: "r"(addr), "r"(cnt) : "memory");
}
__device__ __forceinline__ void mbar_expect_tx(uint32_t addr, uint32_t bytes) {
    asm volatile("mbarrier.arrive.expect_tx.shared.b64 _, [%0], %1;"
                 :: "r"(addr), "r"(bytes) : "memory");
}
__device__ __forceinline__ void mbar_wait(uint32_t addr, uint32_t parity) {
    asm volatile(
        "{\n\t"
        ".reg .pred P;\n\t"
        "WAITLOOP_%=:\n\t"
        "mbarrier.try_wait.parity.acquire.cta.shared::cta.b64 P, [%0], %1, 0x989680;\n\t"
        "@P bra.uni WAITDONE_%=;\n\t"
        "bra.uni WAITLOOP_%=;\n\t"
        "WAITDONE_%=:\n\t"
        "}\n\t"
        :: "r"(addr), "r"(parity) : "memory");
}
__device__ __forceinline__ void cluster_barrier() {
    asm volatile("barrier.cluster.arrive.aligned;" ::: "memory");
    asm volatile("barrier.cluster.wait.aligned;" ::: "memory");
}
// packed fp32 pair math (sm_103a fma.rn.f32x2 — 2 IEEE fp32 FMAs per issue)
__device__ __forceinline__ unsigned long long pack2(float lo, float hi) {
    unsigned long long u;
    asm("mov.b64 %0, {%1, %2};" : "=l"(u) : "f"(lo), "f"(hi));
    return u;
}
__device__ __forceinline__ void unpack2(float& lo, float& hi, unsigned long long u) {
    asm("mov.b64 {%0, %1}, %2;" : "=f"(lo), "=f"(hi) : "l"(u));
}
__device__ __forceinline__ void ffma2(unsigned long long& acc, unsigned long long a,
                                      unsigned long long b) {
    asm("fma.rn.f32x2 %0, %1, %2, %3;" : "=l"(acc) : "l"(a), "l"(b), "l"(acc));
}
union F4U2 { float4 v; unsigned long long u[2]; };

// ---------------- kernel 1: second moments of x over (B,T) ----------------
__global__ void __launch_bounds__(256) stats_kernel(const float* __restrict__ x) {
    __shared__ float red[256];
    float s0=0,s1=0,s2=0,s3=0,s4=0,s5=0,s6=0,s7=0,s8=0;
    const int stride = NSTAT_BLK * 256;
    for (int i = blockIdx.x * 256 + threadIdx.x; i < NROWS; i += stride) {
        float a = x[i*3+0], b = x[i*3+1], c = x[i*3+2];
        s0 += a;   s1 += b;   s2 += c;
        s3 += a*a; s4 += a*b; s5 += a*c;
        s6 += b*b; s7 += b*c; s8 += c*c;
    }
    float sv[9] = {s0,s1,s2,s3,s4,s5,s6,s7,s8};
    #pragma unroll 1
    for (int j = 0; j < 9; j++) {
        red[threadIdx.x] = sv[j];
        __syncthreads();
        for (int o = 128; o > 0; o >>= 1) {
            if (threadIdx.x < o) red[threadIdx.x] += red[threadIdx.x + o];
            __syncthreads();
        }
        if (threadIdx.x == 0) g_part[blockIdx.x * 9 + j] = red[0];
        __syncthreads();
    }
}

// ---------------- kernel 2: fold BN (derived analytically) into conv ----------------
__global__ void __launch_bounds__(64) fold_kernel(const float* __restrict__ conv_w,
                                                  const float* __restrict__ conv_b,
                                                  const float* __restrict__ gamma,
                                                  const float* __restrict__ beta) {
    __shared__ float st[9];
    if (threadIdx.x < 9) {
        float s = 0.f;
        for (int i = 0; i < NSTAT_BLK; i++) s += g_part[i * 9 + threadIdx.x];
        st[threadIdx.x] = s;
    }
    __syncthreads();
    const int c = threadIdx.x;
    const float N = (float)NROWS;
    float m0 = st[0]/N, m1 = st[1]/N, m2 = st[2]/N;
    float C00 = st[3]/N - m0*m0, C01 = st[4]/N - m0*m1, C02 = st[5]/N - m0*m2;
    float C11 = st[6]/N - m1*m1, C12 = st[7]/N - m1*m2, C22 = st[8]/N - m2*m2;
    float w0 = conv_w[c*3+0], w1 = conv_w[c*3+1], w2 = conv_w[c*3+2];
    float mean = w0*m0 + w1*m1 + w2*m2 + conv_b[c];
    float var  = w0*w0*C00 + w1*w1*C11 + w2*w2*C22
               + 2.f*(w0*w1*C01 + w0*w2*C02 + w1*w2*C12);
    float sc = gamma[c] * rsqrtf(var + 1e-5f);
    g_cw[c*3+0] = w0 * sc;
    g_cw[c*3+1] = w1 * sc;
    g_cw[c*3+2] = w2 * sc;
    g_cb[c]     = conv_b[c] * sc + (beta[c] - mean * sc);
}

// ---------------- kernel 3: persistent clustered LSTM ----------------
// 128 CTAs, cluster=(2,1,1): blockIdx.x>>1 = batch row, blockIdx.x&1 = hidden half.
// 256 threads/CTA; thread owns gate row r with W_hh[r][:], W_ih[r][:] packed
// f32x2 in registers (96 register pairs). h exchange via st.async + tx mbarrier.
__global__ void __cluster_dims__(2, 1, 1) __launch_bounds__(256, 1)
lstm_kernel(const float* __restrict__ x,
            const float* __restrict__ w_ih, const float* __restrict__ b_ih,
            const float* __restrict__ w_hh, const float* __restrict__ b_hh,
            const float* __restrict__ out_w, const float* __restrict__ out_b,
            const float* __restrict__ h0, const float* __restrict__ c0,
            float* __restrict__ out) {
    __shared__ __align__(16) float h_s[2][H_];   // double-buffered full h
    __shared__ float c_s[64];                    // own half of c
    __shared__ __align__(16) float y_s[C1_];     // conv/BN/relu output, current step
    __shared__ float act_s[256];                 // activated gates
    __shared__ __align__(8) unsigned long long mbar[1];

    const int tid  = threadIdx.x;
    const int b    = blockIdx.x >> 1;
    const int half = blockIdx.x & 1;
    const int q    = tid >> 6;        // gate: 0=i 1=f 2=g 3=o
    const int jj   = tid & 63;        // hidden index within half
    const int r    = q * H_ + half * 64 + jj;   // global gate row in [0,512)

    // pack weights into f32x2 register pairs (one-time)
    unsigned long long whh2[H_ / 2];
    #pragma unroll
    for (int k = 0; k < H_ / 2; k++) {
        float2 w = ((const float2*)(w_hh + (size_t)r * H_))[k];
        whh2[k] = pack2(w.x, w.y);
    }
    unsigned long long wih2[C1_ / 2];
    #pragma unroll
    for (int k = 0; k < C1_ / 2; k++) {
        float2 w = ((const float2*)(w_ih + (size_t)r * C1_))[k];
        wih2[k] = pack2(w.x, w.y);
    }
    const float bias = b_ih[r] + b_hh[r];

    if (tid < H_) h_s[0][tid] = h0[b * H_ + tid];
    if (tid < 64) c_s[tid] = c0[b * H_ + half * 64 + tid];

    const float* xb = x + (size_t)b * T_ * 3;
    if (tid >= 64 && tid < 128) {   // y(0)
        int ch = tid - 64;
        float v = fmaf(g_cw[ch*3+2], xb[2],
                  fmaf(g_cw[ch*3+1], xb[1],
                  fmaf(g_cw[ch*3+0], xb[0], g_cb[ch])));
        y_s[ch] = fmaxf(v, 0.f);
    }

    const uint32_t mbar_a    = smem_u32(mbar);
    const uint32_t peer_mbar = mapa_u32(mbar_a, (uint32_t)(half ^ 1));
    const uint32_t peer_h    = mapa_u32(smem_u32(&h_s[0][0]), (uint32_t)(half ^ 1));

    if (tid == 0) mbar_init(mbar_a, 1);
    __syncthreads();
    cluster_barrier();   // mbar init visible cluster-wide before any st.async
    if (tid == 0) mbar_expect_tx(mbar_a, 64 * 4);   // phase 0

    uint32_t parity = 0;
    const float* xp = xb + 3;

    #pragma unroll 1
    for (int t = 0; t < T_; t++) {
        // ---- input-side partial gates (no dependence on h -> hides exchange) ----
        unsigned long long acc0 = pack2(bias, 0.f), acc1 = pack2(0.f, 0.f);
        const float4* y4 = (const float4*)y_s;
        #pragma unroll
        for (int c2 = 0; c2 < C1_ / 4; c2++) {
            F4U2 yv; yv.v = y4[c2];
            ffma2(acc0, wih2[2*c2],     yv.u[0]);
            ffma2(acc1, wih2[2*c2 + 1], yv.u[1]);
        }
        // prefetch x(t+1)
        float px0 = 0.f, px1 = 0.f, px2 = 0.f;
        const bool doy = (tid >= 64 && tid < 128 && t < T_ - 1);
        if (doy) { px0 = xp[0]; px1 = xp[1]; px2 = xp[2]; }

        // ---- wait for peer half of h(t); re-arm barrier for next phase ----
        if (t > 0) {
            mbar_wait(mbar_a, parity);
            parity ^= 1;
            if (tid == 0) mbar_expect_tx(mbar_a, 64 * 4);
        }
        const int cur = t & 1;
        const float4* h4 = (const float4*)h_s[cur];
        #pragma unroll
        for (int k2 = 0; k2 < H_ / 4; k2++) {
            F4U2 hv; hv.v = h4[k2];
            ffma2(acc0, whh2[2*k2],     hv.u[0]);
            ffma2(acc1, whh2[2*k2 + 1], hv.u[1]);
        }
        float a0lo, a0hi, a1lo, a1hi;
        unpack2(a0lo, a0hi, acc0);
        unpack2(a1lo, a1hi, acc1);
        float a = (a0lo + a1lo) + (a0hi + a1hi);
        a = (q == 2) ? tanh_fast(a) : sig_fast(a);
        act_s[tid] = a;
        __syncthreads();

        const int nxt = cur ^ 1;
        if (tid < 64) {
            // c/h update for own half; async-push h to peer with tx completion
            float cc = fmaf(act_s[64 + jj], c_s[jj], act_s[jj] * act_s[128 + jj]);
            c_s[jj] = cc;
            float hn = act_s[192 + jj] * tanh_fast(cc);
            int hj = half * 64 + jj;
            h_s[nxt][hj] = hn;
            st_async_remote_f32(peer_h + (uint32_t)(nxt * H_ + hj) * 4u, hn, peer_mbar);
        } else if (doy) {
            // conv+BN+relu for step t+1 (overlaps with the h/c update warps)
            int ch = tid - 64;
            float v = fmaf(g_cw[ch*3+2], px2,
                      fmaf(g_cw[ch*3+1], px1,
                      fmaf(g_cw[ch*3+0], px0, g_cb[ch])));
            y_s[ch] = fmaxf(v, 0.f);
        }
        __syncthreads();
        xp += 3;
    }

    // final exchange: h(T) complete in h_s[0] (T even)
    mbar_wait(mbar_a, parity);

    if (half == 0 && tid < NCLS_) {
        float acc = out_b[tid];
        #pragma unroll 4
        for (int k = 0; k < H_; k++)
            acc = fmaf(h_s[0][k], out_w[tid * H_ + k], acc);
        out[b * NCLS_ + tid] = acc;
    }
    cluster_barrier();   // clean cluster teardown
}

// ---------------- launch ----------------
extern "C" void kernel_launch(void* const* d_in, const int* in_sizes, int n_in,
                              void* d_out, int out_size) {
    const float* x      = (const float*)d_in[0];
    const float* conv_w = (const float*)d_in[1];
    const float* conv_b = (const float*)d_in[2];
    const float* bn_g   = (const float*)d_in[3];
    const float* bn_b   = (const float*)d_in[4];
    const float* w_ih   = (const float*)d_in[5];
    const float* b_ih   = (const float*)d_in[6];
    const float* w_hh   = (const float*)d_in[7];
    const float* b_hh   = (const float*)d_in[8];
    const float* out_w  = (const float*)d_in[9];
    const float* out_b  = (const float*)d_in[10];
    const float* h0     = (const float*)d_in[11];
    const float* c0     = (const float*)d_in[12];
    float* out = (float*)d_out;

    stats_kernel<<<NSTAT_BLK, 256>>>(x);
    fold_kernel<<<1, 64>>>(conv_w, conv_b, bn_g, bn_b);
    lstm_kernel<<<2 * B_, 256>>>(x, w_ih, b_ih, w_hh, b_hh,
                                 out_w, out_b, h0, c0, out);
}